// round 1
// baseline (speedup 1.0000x reference)
#include <cuda_runtime.h>
#include <math.h>

#ifndef M_PI
#define M_PI 3.14159265358979323846
#endif

// ---------------- problem sizes ----------------
#define BB   64      // batch
#define NCHS 10      // selected channels
#define TT   2000    // raw time length
#define PADL 21      // filtfilt pad
#define TE   (TT + 2*PADL)   // 2042 extended length
#define TR   1280    // resampled length
#define DM   16      // d_model
#define NROWS (BB*NCHS)      // 640

__constant__ int d_CH[10] = {126,125,48,112,67,93,10,61,39,108};

// ---------------- scratch (static device globals; no runtime alloc) ----------------
__device__ float  g_mean[BB*TT];
__device__ float  g_yf[NROWS*TT];
__device__ float  g_xr[NROWS*TR];
__device__ float  g_h0[BB*TR*DM];
__device__ float  g_q[BB*TR*DM];
__device__ float  g_k[BB*TR*DM];
__device__ float  g_v[BB*TR*DM];
__device__ float  g_pool[BB*DM];
__device__ float  g_h[526];
__device__ double g_htmp[501];
__device__ float  g_sosb[3][3];
__device__ float  g_sosa[3][2];
__device__ float  g_zi[3][2];
__device__ float  g_pe[TR*DM];

// ---------------- init: filter coefficients, FIR taps, PE table, zero pool ----------------
__device__ __forceinline__ double bessel_i0(double x) {
    double s = 1.0, t = 1.0;
    double x2 = x * x * 0.25;
    for (int k = 1; k < 60; k++) {
        t *= x2 / ((double)k * (double)k);
        s += t;
        if (t < s * 1e-18) break;
    }
    return s;
}

__global__ void eeg_init_kernel() {
    int tid = threadIdx.x;
    // Kaiser-windowed sinc taps (double, matching numpy)
    double i0b = bessel_i0(5.0);
    for (int n = tid; n < 501; n += blockDim.x) {
        double mm  = (double)n - 250.0;
        double fc  = 1.0 / 25.0;
        double xx  = fc * mm;
        double snc = (mm == 0.0) ? 1.0 : (sin(M_PI * xx) / (M_PI * xx));
        double r   = mm / 250.0;
        double w   = bessel_i0(5.0 * sqrt(fmax(0.0, 1.0 - r * r))) / i0b;
        g_htmp[n]  = fc * snc * w;
    }
    // zero pooling accumulator (must happen every graph replay)
    for (int i = tid; i < BB * DM; i += blockDim.x) g_pool[i] = 0.f;
    // positional encoding (float64 sin/cos then cast, matching reference)
    for (int e = tid; e < TR * DM; e += blockDim.x) {
        int pos = e / DM, d = e % DM;
        double div = exp(-((double)(d & ~1)) * log(10000.0) / 16.0);
        double ang = (double)pos * div;
        g_pe[e] = (float)((d & 1) ? cos(ang) : sin(ang));
    }
    __syncthreads();
    if (tid == 0) {
        // normalize FIR, prepend 25 zeros (n_pre_pad), scale by UP=16
        double s = 0.0;
        for (int n = 0; n < 501; n++) s += g_htmp[n];
        for (int i = 0; i < 25; i++) g_h[i] = 0.f;
        for (int n = 0; n < 501; n++) g_h[25 + n] = (float)(g_htmp[n] / s * 16.0);

        // Butterworth highpass order 6, wn = 0.01 (double, then cast like the reference)
        double warped = 4.0 * tan(M_PI * 0.01 / 2.0);
        double pr[6], pim[6];
        for (int i = 0; i < 6; i++) {
            int m = -5 + 2 * i;
            double th = M_PI * (double)m / 12.0;
            double ar = -cos(th), ai = -sin(th);      // analog prototype pole
            double den = ar * ar + ai * ai;           // == 1
            pr[i]  =  warped * ar / den;              // warped / p  (HP transform)
            pim[i] = -warped * ai / den;
        }
        // k = Re(4^6 / prod(4 - p))
        double qr = 1.0, qi = 0.0;
        for (int i = 0; i < 6; i++) {
            double xr = 4.0 - pr[i], xi = -pim[i];
            double nr = qr * xr - qi * xi;
            double ni = qr * xi + qi * xr;
            qr = nr; qi = ni;
        }
        double kk = 4096.0 * qr / (qr * qr + qi * qi);
        // bilinear p_d = (4+p)/(4-p)
        double dr[6], di[6];
        for (int i = 0; i < 6; i++) {
            double nr = 4.0 + pr[i], ni = pim[i];
            double mr = 4.0 - pr[i], mi = -pim[i];
            double dd = mr * mr + mi * mi;
            dr[i] = (nr * mr + ni * mi) / dd;
            di[i] = (ni * mr - nr * mi) / dd;
        }
        // select Im > 0, sort descending by | |p|-1 |
        double sr[3], si[3]; int c = 0;
        for (int i = 0; i < 6; i++) if (di[i] > 0.0) { sr[c] = dr[i]; si[c] = di[i]; c++; }
        double key[3];
        for (int i = 0; i < 3; i++) {
            double mag = sqrt(sr[i] * sr[i] + si[i] * si[i]);
            key[i] = fabs(mag - 1.0);
        }
        int ord[3] = {0, 1, 2};
        for (int a = 0; a < 3; a++)
            for (int b = a + 1; b < 3; b++)
                if (key[ord[b]] > key[ord[a]]) { int t = ord[a]; ord[a] = ord[b]; ord[b] = t; }
        // SOS rows + steady-state zi (sosfilt_zi)
        double zs = 1.0;
        for (int s2 = 0; s2 < 3; s2++) {
            int i = ord[s2];
            double b0 = (s2 == 0) ? kk : 1.0;
            double b1 = -2.0 * b0, b2 = b0;
            double a1 = -2.0 * sr[i];
            double a2 = sr[i] * sr[i] + si[i] * si[i];
            g_sosb[s2][0] = (float)b0; g_sosb[s2][1] = (float)b1; g_sosb[s2][2] = (float)b2;
            g_sosa[s2][0] = (float)a1; g_sosa[s2][1] = (float)a2;
            double det = 1.0 + a1 + a2;
            double B0 = b1 - a1 * b0, B1 = b2 - a2 * b0;
            double z0 = (B0 + B1) / det;
            double z1 = (-a2 * B0 + (1.0 + a1) * B1) / det;
            g_zi[s2][0] = (float)(zs * z0);
            g_zi[s2][1] = (float)(zs * z1);
            zs *= (b0 + b1 + b2) / det;
        }
    }
}

// ---------------- stage 1: mean over selected channels ----------------
__global__ void eeg_mean_kernel(const float* __restrict__ x) {
    int idx = blockIdx.x * blockDim.x + threadIdx.x;
    if (idx >= BB * TT) return;
    int b = idx / TT, t = idx % TT;
    float s = 0.f;
    #pragma unroll
    for (int c = 0; c < 10; c++) s += x[((long)(b * 128 + d_CH[c])) * TT + t];
    g_mean[idx] = s * (1.0f / 10.0f);
}

// ---------------- stage 2: filtfilt (serial biquad cascade per row) ----------------
#define BIQUAD_STEP(v, y0, y1, y2)                                   \
    {                                                                \
        y0 = fmaf(b00, (v), z00);                                    \
        z00 = fmaf(-a01, y0, fmaf(b01, (v), z01));                   \
        z01 = fmaf(-a02, y0, b02 * (v));                             \
        y1 = fmaf(b10, y0, z10);                                     \
        z10 = fmaf(-a11, y1, fmaf(b11, y0, z11));                    \
        z11 = fmaf(-a12, y1, b12 * y0);                              \
        y2 = fmaf(b20, y1, z20);                                     \
        z20 = fmaf(-a21, y2, fmaf(b21, y1, z21));                    \
        z21 = fmaf(-a22, y2, b22 * y1);                              \
    }

__global__ void eeg_filtfilt_kernel(const float* __restrict__ x) {
    __shared__ float e[TE];
    __shared__ float wrk[TE];
    int row = blockIdx.x;
    int b = row / NCHS, c = row % NCHS;
    const float* xp = x + ((long)(b * 128 + d_CH[c])) * TT;
    const float* mp = g_mean + (long)b * TT;
    int tid = threadIdx.x;
    for (int t = tid; t < TT; t += 32) e[PADL + t] = xp[t] - mp[t];
    __syncwarp();
    if (tid < PADL) {
        float v0 = e[PADL], vl = e[PADL + TT - 1];
        e[tid]             = 2.f * v0 - e[PADL + (PADL - tid)];
        e[PADL + TT + tid] = 2.f * vl - e[PADL + (TT - 2 - tid)];
    }
    __syncwarp();
    if (tid == 0) {
        float b00 = g_sosb[0][0], b01 = g_sosb[0][1], b02 = g_sosb[0][2];
        float b10 = g_sosb[1][0], b11 = g_sosb[1][1], b12 = g_sosb[1][2];
        float b20 = g_sosb[2][0], b21 = g_sosb[2][1], b22 = g_sosb[2][2];
        float a01 = g_sosa[0][0], a02 = g_sosa[0][1];
        float a11 = g_sosa[1][0], a12 = g_sosa[1][1];
        float a21 = g_sosa[2][0], a22 = g_sosa[2][1];
        float zi00 = g_zi[0][0], zi01 = g_zi[0][1];
        float zi10 = g_zi[1][0], zi11 = g_zi[1][1];
        float zi20 = g_zi[2][0], zi21 = g_zi[2][1];
        // forward pass: e -> wrk
        float x0 = e[0];
        float z00 = zi00 * x0, z01 = zi01 * x0;
        float z10 = zi10 * x0, z11 = zi11 * x0;
        float z20 = zi20 * x0, z21 = zi21 * x0;
        for (int t = 0; t < TE; t++) {
            float v = e[t], y0, y1, y2;
            BIQUAD_STEP(v, y0, y1, y2);
            wrk[t] = y2;
        }
        // backward pass: reversed wrk -> e
        x0 = wrk[TE - 1];
        z00 = zi00 * x0; z01 = zi01 * x0;
        z10 = zi10 * x0; z11 = zi11 * x0;
        z20 = zi20 * x0; z21 = zi21 * x0;
        for (int t = 0; t < TE; t++) {
            float v = wrk[TE - 1 - t], y0, y1, y2;
            BIQUAD_STEP(v, y0, y1, y2);
            e[t] = y2;
        }
    }
    __syncwarp();
    float* yp = g_yf + (long)row * TT;
    // final output[t] = reversed-pass2[2020 - t] (reverse + crop PADL)
    for (int t = tid; t < TT; t += 32) yp[t] = e[2020 - t];
}

// ---------------- stage 3: polyphase resample + tanh + per-row standardize ----------------
__global__ void eeg_resample_kernel() {
    __shared__ float yf[TT];
    __shared__ float tv[TR];
    __shared__ float hh[526];
    __shared__ float red[128];
    int row = blockIdx.x, tid = threadIdx.x;
    const float* src = g_yf + (long)row * TT;
    for (int t = tid; t < TT; t += 128) yf[t] = src[t];
    for (int i = tid; i < 526; i += 128) hh[i] = g_h[i];
    __syncthreads();
    for (int n = tid; n < TR; n += 128) {
        int A = (n + 11) * 25;
        int tlo = A - 525 + 15;
        tlo = (tlo > 0) ? (tlo >> 4) : 0;
        int thi = A >> 4;
        if (thi > TT - 1) thi = TT - 1;
        float s = 0.f;
        int idx = A - 16 * tlo;
        for (int t = tlo; t <= thi; t++) { s = fmaf(yf[t], hh[idx], s); idx -= 16; }
        tv[n] = tanhf(s);
    }
    __syncthreads();
    float ls = 0.f;
    for (int n = tid; n < TR; n += 128) ls += tv[n];
    red[tid] = ls; __syncthreads();
    for (int st = 64; st > 0; st >>= 1) { if (tid < st) red[tid] += red[tid + st]; __syncthreads(); }
    float mean = red[0] * (1.f / TR);
    __syncthreads();
    float lv = 0.f;
    for (int n = tid; n < TR; n += 128) { float d = tv[n] - mean; lv = fmaf(d, d, lv); }
    red[tid] = lv; __syncthreads();
    for (int st = 64; st > 0; st >>= 1) { if (tid < st) red[tid] += red[tid + st]; __syncthreads(); }
    float var  = red[0] * (1.f / (TR - 1));
    float stdv = fmaxf(sqrtf(var), 1e-6f);
    float inv  = 1.f / stdv;
    float* dst = g_xr + (long)row * TR;
    for (int n = tid; n < TR; n += 128) dst[n] = (tv[n] - mean) * inv;
}

// ---------------- stage 4: conv1d(10->16,k3) + relu + LN0 + PE ----------------
__global__ void eeg_conv_ln_pe_kernel(const float* __restrict__ cw, const float* __restrict__ cb,
                                      const float* __restrict__ ln0g, const float* __restrict__ ln0b) {
    __shared__ float w[480];
    __shared__ float bias[16], sg[16], sb[16];
    int tid = threadIdx.x;
    for (int i = tid; i < 480; i += blockDim.x) w[i] = cw[i];
    if (tid < 16) { bias[tid] = cb[tid]; sg[tid] = ln0g[tid]; sb[tid] = ln0b[tid]; }
    __syncthreads();
    int idx = blockIdx.x * blockDim.x + tid;   // b*TR + n
    if (idx >= BB * TR) return;
    int n = idx % TR;
    float xin[10][3];
    #pragma unroll
    for (int i = 0; i < 10; i++) {
        const float* base = g_xr + ((long)(idx / TR) * NCHS + i) * TR + n;
        xin[i][0] = (n > 0)      ? base[-1] : 0.f;
        xin[i][1] = base[0];
        xin[i][2] = (n < TR - 1) ? base[1]  : 0.f;
    }
    float o[16];
    #pragma unroll
    for (int oc = 0; oc < 16; oc++) {
        float s = bias[oc];
        #pragma unroll
        for (int i = 0; i < 10; i++) {
            s = fmaf(w[oc * 30 + i * 3 + 0], xin[i][0], s);
            s = fmaf(w[oc * 30 + i * 3 + 1], xin[i][1], s);
            s = fmaf(w[oc * 30 + i * 3 + 2], xin[i][2], s);
        }
        o[oc] = fmaxf(s, 0.f);
    }
    float mu = 0.f;
    #pragma unroll
    for (int d = 0; d < 16; d++) mu += o[d];
    mu *= (1.f / 16);
    float var = 0.f;
    #pragma unroll
    for (int d = 0; d < 16; d++) { float dd = o[d] - mu; var = fmaf(dd, dd, var); }
    var *= (1.f / 16);
    float r = rsqrtf(var + 1e-5f);
    float* dst = g_h0 + (long)idx * 16;
    const float* pe = g_pe + n * 16;
    #pragma unroll
    for (int d = 0; d < 16; d++) dst[d] = fmaf((o[d] - mu) * r, sg[d], sb[d]) + pe[d];
}

// ---------------- stage 5: QKV projection (q pre-scaled by 0.25) ----------------
__global__ void eeg_qkv_kernel(const float* __restrict__ wqkv, const float* __restrict__ bqkv) {
    __shared__ float w[768];
    __shared__ float bb[48];
    int tid = threadIdx.x;
    for (int i = tid; i < 768; i += blockDim.x) w[i] = wqkv[i];
    if (tid < 48) bb[tid] = bqkv[tid];
    __syncthreads();
    int idx = blockIdx.x * blockDim.x + tid;   // b*TR + n
    float xv[16];
    const float4* src = (const float4*)(g_h0 + (long)idx * 16);
    float4 t0 = src[0], t1 = src[1], t2 = src[2], t3 = src[3];
    xv[0] = t0.x; xv[1] = t0.y; xv[2] = t0.z; xv[3] = t0.w;
    xv[4] = t1.x; xv[5] = t1.y; xv[6] = t1.z; xv[7] = t1.w;
    xv[8] = t2.x; xv[9] = t2.y; xv[10] = t2.z; xv[11] = t2.w;
    xv[12] = t3.x; xv[13] = t3.y; xv[14] = t3.z; xv[15] = t3.w;
    float* qd = g_q + (long)idx * 16;
    float* kd = g_k + (long)idx * 16;
    float* vd = g_v + (long)idx * 16;
    #pragma unroll
    for (int j = 0; j < 16; j++) {
        float sq = bb[j], sk = bb[16 + j], sv = bb[32 + j];
        #pragma unroll
        for (int d = 0; d < 16; d++) {
            sq = fmaf(w[j * 16 + d],        xv[d], sq);
            sk = fmaf(w[(16 + j) * 16 + d], xv[d], sk);
            sv = fmaf(w[(32 + j) * 16 + d], xv[d], sv);
        }
        qd[j] = sq * 0.25f;   // fold the attention scale into q
        kd[j] = sk;
        vd[j] = sv;
    }
}

// ---------------- LN helper ----------------
__device__ __forceinline__ void ln16(float* v, const float* g, const float* b) {
    float mu = 0.f;
    #pragma unroll
    for (int d = 0; d < 16; d++) mu += v[d];
    mu *= (1.f / 16);
    float var = 0.f;
    #pragma unroll
    for (int d = 0; d < 16; d++) { float dd = v[d] - mu; var = fmaf(dd, dd, var); }
    var *= (1.f / 16);
    float r = rsqrtf(var + 1e-5f);
    #pragma unroll
    for (int d = 0; d < 16; d++) v[d] = fmaf((v[d] - mu) * r, g[d], b[d]);
}

// ---------------- stage 6: flash attention + wo + LN1 + FFN + LN2 + pool ----------------
__global__ void eeg_attn_kernel(const float* __restrict__ wo, const float* __restrict__ bo,
                                const float* __restrict__ w1, const float* __restrict__ b1,
                                const float* __restrict__ w2, const float* __restrict__ b2,
                                const float* __restrict__ l1g, const float* __restrict__ l1b,
                                const float* __restrict__ l2g, const float* __restrict__ l2b) {
    __shared__ float Ks[128 * 16];
    __shared__ float Vs[128 * 16];
    __shared__ float swo[256], sbo[16], sw1[512], sb1[32], sw2[512], sb2[16];
    __shared__ float sl1g[16], sl1b[16], sl2g[16], sl2b[16];
    int tid = threadIdx.x;
    for (int i = tid; i < 256; i += 128) swo[i] = wo[i];
    for (int i = tid; i < 512; i += 128) { sw1[i] = w1[i]; sw2[i] = w2[i]; }
    if (tid < 16) {
        sbo[tid] = bo[tid]; sb2[tid] = b2[tid];
        sl1g[tid] = l1g[tid]; sl1b[tid] = l1b[tid];
        sl2g[tid] = l2g[tid]; sl2b[tid] = l2b[tid];
    }
    if (tid < 32) sb1[tid] = b1[tid];

    int b = blockIdx.x / 10, qt = blockIdx.x % 10;
    int qn = qt * 128 + tid;
    long qbase = ((long)b * TR + qn) * 16;
    float q[16];
    {
        const float4* s = (const float4*)(g_q + qbase);
        float4 a0 = s[0], a1 = s[1], a2 = s[2], a3 = s[3];
        q[0] = a0.x; q[1] = a0.y; q[2] = a0.z; q[3] = a0.w;
        q[4] = a1.x; q[5] = a1.y; q[6] = a1.z; q[7] = a1.w;
        q[8] = a2.x; q[9] = a2.y; q[10] = a2.z; q[11] = a2.w;
        q[12] = a3.x; q[13] = a3.y; q[14] = a3.z; q[15] = a3.w;
    }
    float m = -1e30f, l = 0.f, acc[16];
    #pragma unroll
    for (int d = 0; d < 16; d++) acc[d] = 0.f;

    for (int kb = 0; kb < 10; kb++) {
        __syncthreads();
        long kbase = ((long)b * TR + kb * 128 + tid) * 16;
        {
            const float4* sk = (const float4*)(g_k + kbase);
            float4* dk = (float4*)(Ks + tid * 16);
            dk[0] = sk[0]; dk[1] = sk[1]; dk[2] = sk[2]; dk[3] = sk[3];
            const float4* sv = (const float4*)(g_v + kbase);
            float4* dv = (float4*)(Vs + tid * 16);
            dv[0] = sv[0]; dv[1] = sv[1]; dv[2] = sv[2]; dv[3] = sv[3];
        }
        __syncthreads();
        #pragma unroll 4
        for (int j = 0; j < 128; j++) {
            const float4* kr = (const float4*)(Ks + j * 16);
            float4 k0 = kr[0], k1 = kr[1], k2 = kr[2], k3 = kr[3];
            float s0 = fmaf(q[0], k0.x, fmaf(q[1], k0.y, fmaf(q[2], k0.z, q[3] * k0.w)));
            float s1 = fmaf(q[4], k1.x, fmaf(q[5], k1.y, fmaf(q[6], k1.z, q[7] * k1.w)));
            float s2 = fmaf(q[8], k2.x, fmaf(q[9], k2.y, fmaf(q[10], k2.z, q[11] * k2.w)));
            float s3 = fmaf(q[12], k3.x, fmaf(q[13], k3.y, fmaf(q[14], k3.z, q[15] * k3.w)));
            float s = (s0 + s1) + (s2 + s3);
            if (s > m) {
                float cc = __expf(m - s);
                m = s; l *= cc;
                #pragma unroll
                for (int d = 0; d < 16; d++) acc[d] *= cc;
            }
            float p = __expf(s - m);
            l += p;
            const float4* vr = (const float4*)(Vs + j * 16);
            float4 v0 = vr[0], v1 = vr[1], v2 = vr[2], v3 = vr[3];
            acc[0]  = fmaf(p, v0.x, acc[0]);  acc[1]  = fmaf(p, v0.y, acc[1]);
            acc[2]  = fmaf(p, v0.z, acc[2]);  acc[3]  = fmaf(p, v0.w, acc[3]);
            acc[4]  = fmaf(p, v1.x, acc[4]);  acc[5]  = fmaf(p, v1.y, acc[5]);
            acc[6]  = fmaf(p, v1.z, acc[6]);  acc[7]  = fmaf(p, v1.w, acc[7]);
            acc[8]  = fmaf(p, v2.x, acc[8]);  acc[9]  = fmaf(p, v2.y, acc[9]);
            acc[10] = fmaf(p, v2.z, acc[10]); acc[11] = fmaf(p, v2.w, acc[11]);
            acc[12] = fmaf(p, v3.x, acc[12]); acc[13] = fmaf(p, v3.y, acc[13]);
            acc[14] = fmaf(p, v3.z, acc[14]); acc[15] = fmaf(p, v3.w, acc[15]);
        }
    }
    float inv = 1.f / l;
    float ov[16];
    #pragma unroll
    for (int d = 0; d < 16; d++) ov[d] = acc[d] * inv;
    // a = ov @ wo.T + bo; x1 = LN1(h0 + a)
    float h0v[16];
    {
        const float4* hs = (const float4*)(g_h0 + qbase);
        float4 a0 = hs[0], a1 = hs[1], a2 = hs[2], a3 = hs[3];
        h0v[0] = a0.x; h0v[1] = a0.y; h0v[2] = a0.z; h0v[3] = a0.w;
        h0v[4] = a1.x; h0v[5] = a1.y; h0v[6] = a1.z; h0v[7] = a1.w;
        h0v[8] = a2.x; h0v[9] = a2.y; h0v[10] = a2.z; h0v[11] = a2.w;
        h0v[12] = a3.x; h0v[13] = a3.y; h0v[14] = a3.z; h0v[15] = a3.w;
    }
    float x1[16];
    #pragma unroll
    for (int d = 0; d < 16; d++) {
        float s = sbo[d];
        #pragma unroll
        for (int e = 0; e < 16; e++) s = fmaf(swo[d * 16 + e], ov[e], s);
        x1[d] = h0v[d] + s;
    }
    ln16(x1, sl1g, sl1b);
    // FFN
    float f[16];
    #pragma unroll
    for (int d = 0; d < 16; d++) f[d] = sb2[d];
    #pragma unroll
    for (int j = 0; j < 32; j++) {
        float t = sb1[j];
        #pragma unroll
        for (int e = 0; e < 16; e++) t = fmaf(sw1[j * 16 + e], x1[e], t);
        t = fmaxf(t, 0.f);
        #pragma unroll
        for (int d = 0; d < 16; d++) f[d] = fmaf(sw2[d * 32 + j], t, f[d]);
    }
    float x2[16];
    #pragma unroll
    for (int d = 0; d < 16; d++) x2[d] = x1[d] + f[d];
    ln16(x2, sl2g, sl2b);
    // block-reduce x2 over 128 queries, atomic into pool
    __syncthreads();
    float* R = Ks;   // reuse
    #pragma unroll
    for (int d = 0; d < 16; d++) R[tid * 16 + d] = x2[d];
    __syncthreads();
    for (int st = 64; st > 0; st >>= 1) {
        if (tid < st) {
            #pragma unroll
            for (int d = 0; d < 16; d++) R[tid * 16 + d] += R[(tid + st) * 16 + d];
        }
        __syncthreads();
    }
    if (tid < 16) atomicAdd(&g_pool[b * 16 + tid], R[tid]);
}

// ---------------- stage 7: head ----------------
__global__ void eeg_head_kernel(const float* __restrict__ wfc, const float* __restrict__ bfc,
                                float* __restrict__ out) {
    int b = threadIdx.x;
    if (b < BB) {
        float s = 0.f;
        #pragma unroll
        for (int d = 0; d < 16; d++) s = fmaf(g_pool[b * 16 + d], wfc[d], s);
        out[b] = s * (1.f / (float)TR) + bfc[0];
    }
}

// ---------------- launch ----------------
extern "C" void kernel_launch(void* const* d_in, const int* in_sizes, int n_in,
                              void* d_out, int out_size) {
    const float* x      = (const float*)d_in[0];
    const float* conv_w = (const float*)d_in[1];
    const float* conv_b = (const float*)d_in[2];
    const float* ln0g   = (const float*)d_in[3];
    const float* ln0b   = (const float*)d_in[4];
    const float* wqkv   = (const float*)d_in[5];
    const float* bqkv   = (const float*)d_in[6];
    const float* wo     = (const float*)d_in[7];
    const float* bo     = (const float*)d_in[8];
    const float* w1     = (const float*)d_in[9];
    const float* b1     = (const float*)d_in[10];
    const float* w2     = (const float*)d_in[11];
    const float* b2     = (const float*)d_in[12];
    const float* l1g    = (const float*)d_in[13];
    const float* l1b    = (const float*)d_in[14];
    const float* l2g    = (const float*)d_in[15];
    const float* l2b    = (const float*)d_in[16];
    const float* wfc    = (const float*)d_in[17];
    const float* bfc    = (const float*)d_in[18];
    float* out = (float*)d_out;

    eeg_init_kernel<<<1, 128>>>();
    eeg_mean_kernel<<<(BB * TT + 255) / 256, 256>>>(x);
    eeg_filtfilt_kernel<<<NROWS, 32>>>(x);
    eeg_resample_kernel<<<NROWS, 128>>>();
    eeg_conv_ln_pe_kernel<<<(BB * TR) / 256, 256>>>(conv_w, conv_b, ln0g, ln0b);
    eeg_qkv_kernel<<<(BB * TR) / 128, 128>>>(wqkv, bqkv);
    eeg_attn_kernel<<<NROWS, 128>>>(wo, bo, w1, b1, w2, b2, l1g, l1b, l2g, l2b);
    eeg_head_kernel<<<1, 64>>>(wfc, bfc, out);
}

// round 2
// speedup vs baseline: 2.9264x; 2.9264x over previous
#include <cuda_runtime.h>
#include <math.h>

#ifndef M_PI
#define M_PI 3.14159265358979323846
#endif

// ---------------- problem sizes ----------------
#define BB   64      // batch
#define NCHS 10      // selected channels
#define TT   2000    // raw time length
#define PADL 21      // filtfilt pad
#define TE   (TT + 2*PADL)   // 2042 extended length
#define TR   1280    // resampled length
#define DM   16      // d_model
#define NROWS (BB*NCHS)      // 640

typedef unsigned long long u64;

__constant__ int d_CH[10] = {126,125,48,112,67,93,10,61,39,108};

// ---------------- scratch (static device globals; no runtime alloc) ----------------
__device__ float  g_mean[BB*TT];
__device__ float  g_yf[NROWS*TT];
__device__ float  g_xr[NROWS*TR];
__device__ float  g_h0[BB*TR*DM];
__device__ float  g_q[BB*TR*DM];
__device__ float  g_k[BB*TR*DM];
__device__ float  g_v[BB*TR*DM];
__device__ float  g_pool[BB*DM];
__device__ float  g_pe[TR*DM];

// =====================================================================
// Compile-time (constexpr) filter constants — replaces the runtime
// double-precision init that ran on a single SM every replay.
// =====================================================================
constexpr double PI_D = 3.141592653589793238462643383279502884;

constexpr double c_red(double x) {
    double y = x;
    while (y >  PI_D) y -= 2.0 * PI_D;
    while (y < -PI_D) y += 2.0 * PI_D;
    return y;
}
constexpr double c_sin(double x) {
    double y = c_red(x);
    double y2 = y * y, t = y, s = y;
    for (int k = 1; k <= 26; k++) { t *= -y2 / ((2.0 * k) * (2.0 * k + 1.0)); s += t; }
    return s;
}
constexpr double c_cos(double x) {
    double y = c_red(x);
    double y2 = y * y, t = 1.0, s = 1.0;
    for (int k = 1; k <= 26; k++) { t *= -y2 / ((2.0 * k - 1.0) * (2.0 * k)); s += t; }
    return s;
}
constexpr double c_tan(double x) { return c_sin(x) / c_cos(x); }
constexpr double c_sqrt(double x) {
    if (x <= 0.0) return 0.0;
    double g = (x > 1.0) ? x : 1.0;
    for (int i = 0; i < 80; i++) g = 0.5 * (g + x / g);
    return g;
}
constexpr double c_i0(double x) {
    double s = 1.0, t = 1.0;
    double x2 = x * x * 0.25;
    for (int k = 1; k < 60; k++) {
        t *= x2 / ((double)k * (double)k);
        s += t;
        if (t < s * 1e-18) break;
    }
    return s;
}

struct Fir { float h[526]; };
constexpr Fir make_fir() {
    double ht[501] = {};
    double i0b = c_i0(5.0);
    for (int n = 0; n < 501; n++) {
        double mm  = (double)n - 250.0;
        double fc  = 1.0 / 25.0;
        double xx  = fc * mm;
        double snc = (n == 250) ? 1.0 : (c_sin(PI_D * xx) / (PI_D * xx));
        double r   = mm / 250.0;
        double arg = 1.0 - r * r;
        double w   = c_i0(5.0 * c_sqrt(arg < 0.0 ? 0.0 : arg)) / i0b;
        ht[n] = fc * snc * w;
    }
    double s = 0.0;
    for (int n = 0; n < 501; n++) s += ht[n];
    Fir F{};
    for (int i = 0; i < 25; i++) F.h[i] = 0.0f;
    for (int n = 0; n < 501; n++) F.h[25 + n] = (float)(ht[n] / s * 16.0);
    return F;
}
__device__ const Fir g_fir = make_fir();

struct Coef {
    float sosb[3][3];
    float sosa[3][2];
    float zi[3][2];
};
constexpr Coef make_coef() {
    double warped = 4.0 * c_tan(PI_D * 0.01 / 2.0);
    double pr[6] = {}, pim[6] = {};
    for (int i = 0; i < 6; i++) {
        int m = -5 + 2 * i;
        double th = PI_D * (double)m / 12.0;
        double ar = -c_cos(th), ai = -c_sin(th);
        double den = ar * ar + ai * ai;
        pr[i]  =  warped * ar / den;
        pim[i] = -warped * ai / den;
    }
    double qr = 1.0, qi = 0.0;
    for (int i = 0; i < 6; i++) {
        double xr = 4.0 - pr[i], xi = -pim[i];
        double nr = qr * xr - qi * xi;
        double ni = qr * xi + qi * xr;
        qr = nr; qi = ni;
    }
    double kk = 4096.0 * qr / (qr * qr + qi * qi);
    double dr[6] = {}, di[6] = {};
    for (int i = 0; i < 6; i++) {
        double nr = 4.0 + pr[i], ni = pim[i];
        double mr = 4.0 - pr[i], mi = -pim[i];
        double dd = mr * mr + mi * mi;
        dr[i] = (nr * mr + ni * mi) / dd;
        di[i] = (ni * mr - nr * mi) / dd;
    }
    double sr[3] = {}, si[3] = {}; int c = 0;
    for (int i = 0; i < 6; i++) if (di[i] > 0.0) { sr[c] = dr[i]; si[c] = di[i]; c++; }
    double key[3] = {};
    for (int i = 0; i < 3; i++) {
        double mag = c_sqrt(sr[i] * sr[i] + si[i] * si[i]);
        double dv = mag - 1.0;
        key[i] = dv < 0.0 ? -dv : dv;
    }
    int ord[3] = {0, 1, 2};
    for (int a = 0; a < 3; a++)
        for (int b = a + 1; b < 3; b++)
            if (key[ord[b]] > key[ord[a]]) { int t = ord[a]; ord[a] = ord[b]; ord[b] = t; }
    Coef C{};
    double zs = 1.0;
    for (int s2 = 0; s2 < 3; s2++) {
        int i = ord[s2];
        double b0 = (s2 == 0) ? kk : 1.0;
        double b1 = -2.0 * b0, b2 = b0;
        double a1 = -2.0 * sr[i];
        double a2 = sr[i] * sr[i] + si[i] * si[i];
        C.sosb[s2][0] = (float)b0; C.sosb[s2][1] = (float)b1; C.sosb[s2][2] = (float)b2;
        C.sosa[s2][0] = (float)a1; C.sosa[s2][1] = (float)a2;
        double det = 1.0 + a1 + a2;
        double B0 = b1 - a1 * b0, B1 = b2 - a2 * b0;
        double z0 = (B0 + B1) / det;
        double z1 = (-a2 * B0 + (1.0 + a1) * B1) / det;
        C.zi[s2][0] = (float)(zs * z0);
        C.zi[s2][1] = (float)(zs * z1);
        zs *= (b0 + b1 + b2) / det;
    }
    return C;
}
__device__ const Coef g_coef = make_coef();

// ---------------- packed f32x2 helpers (Blackwell) ----------------
__device__ __forceinline__ u64 fma2(u64 a, u64 b, u64 c) {
    u64 d; asm("fma.rn.f32x2 %0, %1, %2, %3;" : "=l"(d) : "l"(a), "l"(b), "l"(c)); return d;
}
__device__ __forceinline__ u64 mul2(u64 a, u64 b) {
    u64 d; asm("mul.rn.f32x2 %0, %1, %2;" : "=l"(d) : "l"(a), "l"(b)); return d;
}
__device__ __forceinline__ u64 pack2(float lo, float hi) {
    u64 r; asm("mov.b64 %0, {%1, %2};" : "=l"(r) : "f"(lo), "f"(hi)); return r;
}
__device__ __forceinline__ void unpack2(u64 v, float& lo, float& hi) {
    asm("mov.b64 {%0, %1}, %2;" : "=f"(lo), "=f"(hi) : "l"(v));
}
__device__ __forceinline__ float ex2f(float x) {
    float y; asm("ex2.approx.ftz.f32 %0, %1;" : "=f"(y) : "f"(x)); return y;
}

// ---------------- init: PE table (spread over grid) + pool zero ----------------
__global__ void eeg_init_pe_kernel() {
    int e = blockIdx.x * blockDim.x + threadIdx.x;
    if (e < TR * DM) {
        int pos = e / DM, d = e % DM;
        double div = exp(-((double)(d & ~1)) * log(10000.0) / 16.0);
        double ang = (double)pos * div;
        g_pe[e] = (float)((d & 1) ? cos(ang) : sin(ang));
    }
}
__global__ void eeg_zero_pool_kernel() {
    int i = threadIdx.x;
    if (i < BB * DM) g_pool[i] = 0.f;
}

// ---------------- stage 1: mean over selected channels ----------------
__global__ void eeg_mean_kernel(const float* __restrict__ x) {
    int idx = blockIdx.x * blockDim.x + threadIdx.x;
    if (idx >= BB * TT) return;
    int b = idx / TT, t = idx % TT;
    float s = 0.f;
    #pragma unroll
    for (int c = 0; c < 10; c++) s += x[((long)(b * 128 + d_CH[c])) * TT + t];
    g_mean[idx] = s * (1.0f / 10.0f);
}

// ---------------- stage 2: filtfilt (serial biquad cascade per row) ----------------
#define BIQUAD_STEP(v, y0, y1, y2)                                   \
    {                                                                \
        y0 = fmaf(b00, (v), z00);                                    \
        z00 = fmaf(-a01, y0, fmaf(b01, (v), z01));                   \
        z01 = fmaf(-a02, y0, b02 * (v));                             \
        y1 = fmaf(b10, y0, z10);                                     \
        z10 = fmaf(-a11, y1, fmaf(b11, y0, z11));                    \
        z11 = fmaf(-a12, y1, b12 * y0);                              \
        y2 = fmaf(b20, y1, z20);                                     \
        z20 = fmaf(-a21, y2, fmaf(b21, y1, z21));                    \
        z21 = fmaf(-a22, y2, b22 * y1);                              \
    }

__global__ void eeg_filtfilt_kernel(const float* __restrict__ x) {
    __shared__ float e[TE];
    __shared__ float wrk[TE];
    int row = blockIdx.x;
    int b = row / NCHS, c = row % NCHS;
    const float* xp = x + ((long)(b * 128 + d_CH[c])) * TT;
    const float* mp = g_mean + (long)b * TT;
    int tid = threadIdx.x;
    for (int t = tid; t < TT; t += 32) e[PADL + t] = xp[t] - mp[t];
    __syncwarp();
    if (tid < PADL) {
        float v0 = e[PADL], vl = e[PADL + TT - 1];
        e[tid]             = 2.f * v0 - e[PADL + (PADL - tid)];
        e[PADL + TT + tid] = 2.f * vl - e[PADL + (TT - 2 - tid)];
    }
    __syncwarp();
    if (tid == 0) {
        float b00 = g_coef.sosb[0][0], b01 = g_coef.sosb[0][1], b02 = g_coef.sosb[0][2];
        float b10 = g_coef.sosb[1][0], b11 = g_coef.sosb[1][1], b12 = g_coef.sosb[1][2];
        float b20 = g_coef.sosb[2][0], b21 = g_coef.sosb[2][1], b22 = g_coef.sosb[2][2];
        float a01 = g_coef.sosa[0][0], a02 = g_coef.sosa[0][1];
        float a11 = g_coef.sosa[1][0], a12 = g_coef.sosa[1][1];
        float a21 = g_coef.sosa[2][0], a22 = g_coef.sosa[2][1];
        float zi00 = g_coef.zi[0][0], zi01 = g_coef.zi[0][1];
        float zi10 = g_coef.zi[1][0], zi11 = g_coef.zi[1][1];
        float zi20 = g_coef.zi[2][0], zi21 = g_coef.zi[2][1];
        float x0 = e[0];
        float z00 = zi00 * x0, z01 = zi01 * x0;
        float z10 = zi10 * x0, z11 = zi11 * x0;
        float z20 = zi20 * x0, z21 = zi21 * x0;
        for (int t = 0; t < TE; t++) {
            float v = e[t], y0, y1, y2;
            BIQUAD_STEP(v, y0, y1, y2);
            wrk[t] = y2;
        }
        x0 = wrk[TE - 1];
        z00 = zi00 * x0; z01 = zi01 * x0;
        z10 = zi10 * x0; z11 = zi11 * x0;
        z20 = zi20 * x0; z21 = zi21 * x0;
        for (int t = 0; t < TE; t++) {
            float v = wrk[TE - 1 - t], y0, y1, y2;
            BIQUAD_STEP(v, y0, y1, y2);
            e[t] = y2;
        }
    }
    __syncwarp();
    float* yp = g_yf + (long)row * TT;
    for (int t = tid; t < TT; t += 32) yp[t] = e[2020 - t];
}

// ---------------- stage 3: polyphase resample + tanh + per-row standardize ----------------
__global__ void eeg_resample_kernel() {
    __shared__ float yf[TT];
    __shared__ float tv[TR];
    __shared__ float hh[526];
    __shared__ float red[128];
    int row = blockIdx.x, tid = threadIdx.x;
    const float* src = g_yf + (long)row * TT;
    for (int t = tid; t < TT; t += 128) yf[t] = src[t];
    for (int i = tid; i < 526; i += 128) hh[i] = g_fir.h[i];
    __syncthreads();
    for (int n = tid; n < TR; n += 128) {
        int A = (n + 11) * 25;
        int tlo = A - 525 + 15;
        tlo = (tlo > 0) ? (tlo >> 4) : 0;
        int thi = A >> 4;
        if (thi > TT - 1) thi = TT - 1;
        float s0 = 0.f, s1 = 0.f, s2 = 0.f, s3 = 0.f;
        int t = tlo, idx = A - 16 * tlo;
        for (; t + 3 <= thi; t += 4, idx -= 64) {
            s0 = fmaf(yf[t],     hh[idx],      s0);
            s1 = fmaf(yf[t + 1], hh[idx - 16], s1);
            s2 = fmaf(yf[t + 2], hh[idx - 32], s2);
            s3 = fmaf(yf[t + 3], hh[idx - 48], s3);
        }
        for (; t <= thi; t++, idx -= 16) s0 = fmaf(yf[t], hh[idx], s0);
        tv[n] = tanhf((s0 + s1) + (s2 + s3));
    }
    __syncthreads();
    float ls = 0.f;
    for (int n = tid; n < TR; n += 128) ls += tv[n];
    red[tid] = ls; __syncthreads();
    for (int st = 64; st > 0; st >>= 1) { if (tid < st) red[tid] += red[tid + st]; __syncthreads(); }
    float mean = red[0] * (1.f / TR);
    __syncthreads();
    float lv = 0.f;
    for (int n = tid; n < TR; n += 128) { float d = tv[n] - mean; lv = fmaf(d, d, lv); }
    red[tid] = lv; __syncthreads();
    for (int st = 64; st > 0; st >>= 1) { if (tid < st) red[tid] += red[tid + st]; __syncthreads(); }
    float var  = red[0] * (1.f / (TR - 1));
    float stdv = fmaxf(sqrtf(var), 1e-6f);
    float inv  = 1.f / stdv;
    float* dst = g_xr + (long)row * TR;
    for (int n = tid; n < TR; n += 128) dst[n] = (tv[n] - mean) * inv;
}

// ---------------- stage 4: conv1d(10->16,k3) + relu + LN0 + PE ----------------
__global__ void eeg_conv_ln_pe_kernel(const float* __restrict__ cw, const float* __restrict__ cb,
                                      const float* __restrict__ ln0g, const float* __restrict__ ln0b) {
    __shared__ float w[480];
    __shared__ float bias[16], sg[16], sb[16];
    int tid = threadIdx.x;
    for (int i = tid; i < 480; i += blockDim.x) w[i] = cw[i];
    if (tid < 16) { bias[tid] = cb[tid]; sg[tid] = ln0g[tid]; sb[tid] = ln0b[tid]; }
    __syncthreads();
    int idx = blockIdx.x * blockDim.x + tid;   // b*TR + n
    if (idx >= BB * TR) return;
    int n = idx % TR;
    float xin[10][3];
    #pragma unroll
    for (int i = 0; i < 10; i++) {
        const float* base = g_xr + ((long)(idx / TR) * NCHS + i) * TR + n;
        xin[i][0] = (n > 0)      ? base[-1] : 0.f;
        xin[i][1] = base[0];
        xin[i][2] = (n < TR - 1) ? base[1]  : 0.f;
    }
    float o[16];
    #pragma unroll
    for (int oc = 0; oc < 16; oc++) {
        float s = bias[oc];
        #pragma unroll
        for (int i = 0; i < 10; i++) {
            s = fmaf(w[oc * 30 + i * 3 + 0], xin[i][0], s);
            s = fmaf(w[oc * 30 + i * 3 + 1], xin[i][1], s);
            s = fmaf(w[oc * 30 + i * 3 + 2], xin[i][2], s);
        }
        o[oc] = fmaxf(s, 0.f);
    }
    float mu = 0.f;
    #pragma unroll
    for (int d = 0; d < 16; d++) mu += o[d];
    mu *= (1.f / 16);
    float var = 0.f;
    #pragma unroll
    for (int d = 0; d < 16; d++) { float dd = o[d] - mu; var = fmaf(dd, dd, var); }
    var *= (1.f / 16);
    float r = rsqrtf(var + 1e-5f);
    float* dst = g_h0 + (long)idx * 16;
    const float* pe = g_pe + n * 16;
    #pragma unroll
    for (int d = 0; d < 16; d++) dst[d] = fmaf((o[d] - mu) * r, sg[d], sb[d]) + pe[d];
}

// ---------------- stage 5: QKV projection (q pre-scaled by 0.25*log2e) ----------------
__global__ void eeg_qkv_kernel(const float* __restrict__ wqkv, const float* __restrict__ bqkv) {
    __shared__ float w[768];
    __shared__ float bb[48];
    int tid = threadIdx.x;
    for (int i = tid; i < 768; i += blockDim.x) w[i] = wqkv[i];
    if (tid < 48) bb[tid] = bqkv[tid];
    __syncthreads();
    int idx = blockIdx.x * blockDim.x + tid;   // b*TR + n
    float xv[16];
    const float4* src = (const float4*)(g_h0 + (long)idx * 16);
    float4 t0 = src[0], t1 = src[1], t2 = src[2], t3 = src[3];
    xv[0] = t0.x; xv[1] = t0.y; xv[2] = t0.z; xv[3] = t0.w;
    xv[4] = t1.x; xv[5] = t1.y; xv[6] = t1.z; xv[7] = t1.w;
    xv[8] = t2.x; xv[9] = t2.y; xv[10] = t2.z; xv[11] = t2.w;
    xv[12] = t3.x; xv[13] = t3.y; xv[14] = t3.z; xv[15] = t3.w;
    float* qd = g_q + (long)idx * 16;
    float* kd = g_k + (long)idx * 16;
    float* vd = g_v + (long)idx * 16;
    const float QSCALE = 0.25f * 1.4426950408889634f;   // fold softmax scale + log2(e)
    #pragma unroll
    for (int j = 0; j < 16; j++) {
        float sq = bb[j], sk = bb[16 + j], sv = bb[32 + j];
        #pragma unroll
        for (int d = 0; d < 16; d++) {
            sq = fmaf(w[j * 16 + d],        xv[d], sq);
            sk = fmaf(w[(16 + j) * 16 + d], xv[d], sk);
            sv = fmaf(w[(32 + j) * 16 + d], xv[d], sv);
        }
        qd[j] = sq * QSCALE;
        kd[j] = sk;
        vd[j] = sv;
    }
}

// ---------------- LN helper ----------------
__device__ __forceinline__ void ln16(float* v, const float* g, const float* b) {
    float mu = 0.f;
    #pragma unroll
    for (int d = 0; d < 16; d++) mu += v[d];
    mu *= (1.f / 16);
    float var = 0.f;
    #pragma unroll
    for (int d = 0; d < 16; d++) { float dd = v[d] - mu; var = fmaf(dd, dd, var); }
    var *= (1.f / 16);
    float r = rsqrtf(var + 1e-5f);
    #pragma unroll
    for (int d = 0; d < 16; d++) v[d] = fmaf((v[d] - mu) * r, g[d], b[d]);
}

// ---------------- stage 6: attention (no online max; f32x2 packed math)
//                  + wo + LN1 + FFN + LN2 + pool ----------------
__global__ void eeg_attn_kernel(const float* __restrict__ wo, const float* __restrict__ bo,
                                const float* __restrict__ w1, const float* __restrict__ b1,
                                const float* __restrict__ w2, const float* __restrict__ b2,
                                const float* __restrict__ l1g, const float* __restrict__ l1b,
                                const float* __restrict__ l2g, const float* __restrict__ l2b) {
    __shared__ __align__(16) float Ks[128 * 16];
    __shared__ __align__(16) float Vs[128 * 16];
    __shared__ float swo[256], sbo[16], sw1[512], sb1[32], sw2[512], sb2[16];
    __shared__ float sl1g[16], sl1b[16], sl2g[16], sl2b[16];
    int tid = threadIdx.x;
    for (int i = tid; i < 256; i += 128) swo[i] = wo[i];
    for (int i = tid; i < 512; i += 128) { sw1[i] = w1[i]; sw2[i] = w2[i]; }
    if (tid < 16) {
        sbo[tid] = bo[tid]; sb2[tid] = b2[tid];
        sl1g[tid] = l1g[tid]; sl1b[tid] = l1b[tid];
        sl2g[tid] = l2g[tid]; sl2b[tid] = l2b[tid];
    }
    if (tid < 32) sb1[tid] = b1[tid];

    int b = blockIdx.x / 10, qt = blockIdx.x % 10;
    int qn = qt * 128 + tid;
    long qbase = ((long)b * TR + qn) * 16;

    // q packed as 8 f32x2
    u64 q2[8];
    {
        const ulonglong2* s = (const ulonglong2*)(g_q + qbase);
        ulonglong2 a0 = s[0], a1 = s[1], a2 = s[2], a3 = s[3];
        q2[0] = a0.x; q2[1] = a0.y; q2[2] = a1.x; q2[3] = a1.y;
        q2[4] = a2.x; q2[5] = a2.y; q2[6] = a3.x; q2[7] = a3.y;
    }
    u64 acc2[8];
    u64 zero2 = pack2(0.f, 0.f);
    #pragma unroll
    for (int d = 0; d < 8; d++) acc2[d] = zero2;
    float l = 0.f;

    for (int kb = 0; kb < 10; kb++) {
        __syncthreads();
        long kbase = ((long)b * TR + kb * 128 + tid) * 16;
        {
            const float4* sk = (const float4*)(g_k + kbase);
            float4* dk = (float4*)(Ks + tid * 16);
            dk[0] = sk[0]; dk[1] = sk[1]; dk[2] = sk[2]; dk[3] = sk[3];
            const float4* sv = (const float4*)(g_v + kbase);
            float4* dv = (float4*)(Vs + tid * 16);
            dv[0] = sv[0]; dv[1] = sv[1]; dv[2] = sv[2]; dv[3] = sv[3];
        }
        __syncthreads();
        #pragma unroll 2
        for (int j = 0; j < 128; j++) {
            const ulonglong2* kr = (const ulonglong2*)(Ks + j * 16);
            ulonglong2 ka = kr[0], kc = kr[1], ke = kr[2], kg = kr[3];
            u64 sa = mul2(q2[0], ka.x);
            u64 sb_ = mul2(q2[4], ke.x);
            sa  = fma2(q2[1], ka.y, sa);
            sb_ = fma2(q2[5], ke.y, sb_);
            sa  = fma2(q2[2], kc.x, sa);
            sb_ = fma2(q2[6], kg.x, sb_);
            sa  = fma2(q2[3], kc.y, sa);
            sb_ = fma2(q2[7], kg.y, sb_);
            float a0, a1, b0, b1;
            unpack2(sa, a0, a1);
            unpack2(sb_, b0, b1);
            float s = (a0 + a1) + (b0 + b1);   // already in log2 domain
            float p = ex2f(s);
            l += p;
            u64 p2 = pack2(p, p);
            const ulonglong2* vr = (const ulonglong2*)(Vs + j * 16);
            ulonglong2 va = vr[0], vc = vr[1], ve = vr[2], vg = vr[3];
            acc2[0] = fma2(p2, va.x, acc2[0]);
            acc2[1] = fma2(p2, va.y, acc2[1]);
            acc2[2] = fma2(p2, vc.x, acc2[2]);
            acc2[3] = fma2(p2, vc.y, acc2[3]);
            acc2[4] = fma2(p2, ve.x, acc2[4]);
            acc2[5] = fma2(p2, ve.y, acc2[5]);
            acc2[6] = fma2(p2, vg.x, acc2[6]);
            acc2[7] = fma2(p2, vg.y, acc2[7]);
        }
    }
    float inv = 1.f / l;
    float ov[16];
    #pragma unroll
    for (int d = 0; d < 8; d++) {
        float lo, hi;
        unpack2(acc2[d], lo, hi);
        ov[2 * d]     = lo * inv;
        ov[2 * d + 1] = hi * inv;
    }
    // a = ov @ wo.T + bo; x1 = LN1(h0 + a)
    float h0v[16];
    {
        const float4* hs = (const float4*)(g_h0 + qbase);
        float4 a0 = hs[0], a1 = hs[1], a2 = hs[2], a3 = hs[3];
        h0v[0] = a0.x; h0v[1] = a0.y; h0v[2] = a0.z; h0v[3] = a0.w;
        h0v[4] = a1.x; h0v[5] = a1.y; h0v[6] = a1.z; h0v[7] = a1.w;
        h0v[8] = a2.x; h0v[9] = a2.y; h0v[10] = a2.z; h0v[11] = a2.w;
        h0v[12] = a3.x; h0v[13] = a3.y; h0v[14] = a3.z; h0v[15] = a3.w;
    }
    float x1[16];
    #pragma unroll
    for (int d = 0; d < 16; d++) {
        float s = sbo[d];
        #pragma unroll
        for (int e = 0; e < 16; e++) s = fmaf(swo[d * 16 + e], ov[e], s);
        x1[d] = h0v[d] + s;
    }
    ln16(x1, sl1g, sl1b);
    // FFN
    float f[16];
    #pragma unroll
    for (int d = 0; d < 16; d++) f[d] = sb2[d];
    #pragma unroll
    for (int j = 0; j < 32; j++) {
        float t = sb1[j];
        #pragma unroll
        for (int e = 0; e < 16; e++) t = fmaf(sw1[j * 16 + e], x1[e], t);
        t = fmaxf(t, 0.f);
        #pragma unroll
        for (int d = 0; d < 16; d++) f[d] = fmaf(sw2[d * 32 + j], t, f[d]);
    }
    float x2[16];
    #pragma unroll
    for (int d = 0; d < 16; d++) x2[d] = x1[d] + f[d];
    ln16(x2, sl2g, sl2b);
    // block-reduce x2 over 128 queries, atomic into pool
    __syncthreads();
    float* R = Ks;   // reuse
    #pragma unroll
    for (int d = 0; d < 16; d++) R[tid * 16 + d] = x2[d];
    __syncthreads();
    for (int st = 64; st > 0; st >>= 1) {
        if (tid < st) {
            #pragma unroll
            for (int d = 0; d < 16; d++) R[tid * 16 + d] += R[(tid + st) * 16 + d];
        }
        __syncthreads();
    }
    if (tid < 16) atomicAdd(&g_pool[b * 16 + tid], R[tid]);
}

// ---------------- stage 7: head ----------------
__global__ void eeg_head_kernel(const float* __restrict__ wfc, const float* __restrict__ bfc,
                                float* __restrict__ out) {
    int b = threadIdx.x;
    if (b < BB) {
        float s = 0.f;
        #pragma unroll
        for (int d = 0; d < 16; d++) s = fmaf(g_pool[b * 16 + d], wfc[d], s);
        out[b] = s * (1.f / (float)TR) + bfc[0];
    }
}

// ---------------- launch ----------------
extern "C" void kernel_launch(void* const* d_in, const int* in_sizes, int n_in,
                              void* d_out, int out_size) {
    const float* x      = (const float*)d_in[0];
    const float* conv_w = (const float*)d_in[1];
    const float* conv_b = (const float*)d_in[2];
    const float* ln0g   = (const float*)d_in[3];
    const float* ln0b   = (const float*)d_in[4];
    const float* wqkv   = (const float*)d_in[5];
    const float* bqkv   = (const float*)d_in[6];
    const float* wo     = (const float*)d_in[7];
    const float* bo     = (const float*)d_in[8];
    const float* w1     = (const float*)d_in[9];
    const float* b1     = (const float*)d_in[10];
    const float* w2     = (const float*)d_in[11];
    const float* b2     = (const float*)d_in[12];
    const float* l1g    = (const float*)d_in[13];
    const float* l1b    = (const float*)d_in[14];
    const float* l2g    = (const float*)d_in[15];
    const float* l2b    = (const float*)d_in[16];
    const float* wfc    = (const float*)d_in[17];
    const float* bfc    = (const float*)d_in[18];
    float* out = (float*)d_out;

    eeg_init_pe_kernel<<<(TR * DM + 127) / 128, 128>>>();
    eeg_zero_pool_kernel<<<1, 1024>>>();
    eeg_mean_kernel<<<(BB * TT + 255) / 256, 256>>>(x);
    eeg_filtfilt_kernel<<<NROWS, 32>>>(x);
    eeg_resample_kernel<<<NROWS, 128>>>();
    eeg_conv_ln_pe_kernel<<<(BB * TR) / 256, 256>>>(conv_w, conv_b, ln0g, ln0b);
    eeg_qkv_kernel<<<(BB * TR) / 128, 128>>>(wqkv, bqkv);
    eeg_attn_kernel<<<NROWS, 128>>>(wo, bo, w1, b1, w2, b2, l1g, l1b, l2g, l2b);
    eeg_head_kernel<<<1, 64>>>(wfc, bfc, out);
}

// round 3
// speedup vs baseline: 3.0446x; 1.0404x over previous
#include <cuda_runtime.h>
#include <math.h>

#ifndef M_PI
#define M_PI 3.14159265358979323846
#endif

// ---------------- problem sizes ----------------
#define BB   64      // batch
#define NCHS 10      // selected channels
#define TT   2000    // raw time length
#define PADL 21      // filtfilt pad
#define TE   (TT + 2*PADL)   // 2042 extended length
#define TEP  2080    // padded (prefetch overrun slack)
#define TR   1280    // resampled length
#define DM   16      // d_model
#define NROWS (BB*NCHS)      // 640
#define PF   32      // IIR prefetch depth

typedef unsigned long long u64;

__constant__ int d_CH[10] = {126,125,48,112,67,93,10,61,39,108};

// ---------------- scratch (static device globals; no runtime alloc) ----------------
__device__ float  g_mean[BB*TT];
__device__ float  g_extT[TEP*NROWS];   // transposed: [t][row]
__device__ float  g_wrkT[TEP*NROWS];   // transposed: [t][row]
__device__ float  g_yfT[TT*NROWS];     // transposed: [tau][row]
__device__ float  g_xr[NROWS*TR];
__device__ float  g_h0[BB*TR*DM];
__device__ float  g_q[BB*TR*DM];
__device__ float  g_k[BB*TR*DM];
__device__ float  g_v[BB*TR*DM];
__device__ float  g_pool[BB*DM];
__device__ float  g_pe[TR*DM];

// =====================================================================
// Compile-time (constexpr) filter constants
// =====================================================================
constexpr double PI_D = 3.141592653589793238462643383279502884;

constexpr double c_red(double x) {
    double y = x;
    while (y >  PI_D) y -= 2.0 * PI_D;
    while (y < -PI_D) y += 2.0 * PI_D;
    return y;
}
constexpr double c_sin(double x) {
    double y = c_red(x);
    double y2 = y * y, t = y, s = y;
    for (int k = 1; k <= 26; k++) { t *= -y2 / ((2.0 * k) * (2.0 * k + 1.0)); s += t; }
    return s;
}
constexpr double c_cos(double x) {
    double y = c_red(x);
    double y2 = y * y, t = 1.0, s = 1.0;
    for (int k = 1; k <= 26; k++) { t *= -y2 / ((2.0 * k - 1.0) * (2.0 * k)); s += t; }
    return s;
}
constexpr double c_tan(double x) { return c_sin(x) / c_cos(x); }
constexpr double c_sqrt(double x) {
    if (x <= 0.0) return 0.0;
    double g = (x > 1.0) ? x : 1.0;
    for (int i = 0; i < 80; i++) g = 0.5 * (g + x / g);
    return g;
}
constexpr double c_i0(double x) {
    double s = 1.0, t = 1.0;
    double x2 = x * x * 0.25;
    for (int k = 1; k < 60; k++) {
        t *= x2 / ((double)k * (double)k);
        s += t;
        if (t < s * 1e-18) break;
    }
    return s;
}

struct Fir { float h[526]; };
constexpr Fir make_fir() {
    double ht[501] = {};
    double i0b = c_i0(5.0);
    for (int n = 0; n < 501; n++) {
        double mm  = (double)n - 250.0;
        double fc  = 1.0 / 25.0;
        double xx  = fc * mm;
        double snc = (n == 250) ? 1.0 : (c_sin(PI_D * xx) / (PI_D * xx));
        double r   = mm / 250.0;
        double arg = 1.0 - r * r;
        double w   = c_i0(5.0 * c_sqrt(arg < 0.0 ? 0.0 : arg)) / i0b;
        ht[n] = fc * snc * w;
    }
    double s = 0.0;
    for (int n = 0; n < 501; n++) s += ht[n];
    Fir F{};
    for (int i = 0; i < 25; i++) F.h[i] = 0.0f;
    for (int n = 0; n < 501; n++) F.h[25 + n] = (float)(ht[n] / s * 16.0);
    return F;
}
__device__ const Fir g_fir = make_fir();

struct Coef {
    float sosb[3][3];
    float sosa[3][2];
    float zi[3][2];
};
constexpr Coef make_coef() {
    double warped = 4.0 * c_tan(PI_D * 0.01 / 2.0);
    double pr[6] = {}, pim[6] = {};
    for (int i = 0; i < 6; i++) {
        int m = -5 + 2 * i;
        double th = PI_D * (double)m / 12.0;
        double ar = -c_cos(th), ai = -c_sin(th);
        double den = ar * ar + ai * ai;
        pr[i]  =  warped * ar / den;
        pim[i] = -warped * ai / den;
    }
    double qr = 1.0, qi = 0.0;
    for (int i = 0; i < 6; i++) {
        double xr = 4.0 - pr[i], xi = -pim[i];
        double nr = qr * xr - qi * xi;
        double ni = qr * xi + qi * xr;
        qr = nr; qi = ni;
    }
    double kk = 4096.0 * qr / (qr * qr + qi * qi);
    double dr[6] = {}, di[6] = {};
    for (int i = 0; i < 6; i++) {
        double nr = 4.0 + pr[i], ni = pim[i];
        double mr = 4.0 - pr[i], mi = -pim[i];
        double dd = mr * mr + mi * mi;
        dr[i] = (nr * mr + ni * mi) / dd;
        di[i] = (ni * mr - nr * mi) / dd;
    }
    double sr[3] = {}, si[3] = {}; int c = 0;
    for (int i = 0; i < 6; i++) if (di[i] > 0.0) { sr[c] = dr[i]; si[c] = di[i]; c++; }
    double key[3] = {};
    for (int i = 0; i < 3; i++) {
        double mag = c_sqrt(sr[i] * sr[i] + si[i] * si[i]);
        double dv = mag - 1.0;
        key[i] = dv < 0.0 ? -dv : dv;
    }
    int ord[3] = {0, 1, 2};
    for (int a = 0; a < 3; a++)
        for (int b = a + 1; b < 3; b++)
            if (key[ord[b]] > key[ord[a]]) { int t = ord[a]; ord[a] = ord[b]; ord[b] = t; }
    Coef C{};
    double zs = 1.0;
    for (int s2 = 0; s2 < 3; s2++) {
        int i = ord[s2];
        double b0 = (s2 == 0) ? kk : 1.0;
        double b1 = -2.0 * b0, b2 = b0;
        double a1 = -2.0 * sr[i];
        double a2 = sr[i] * sr[i] + si[i] * si[i];
        C.sosb[s2][0] = (float)b0; C.sosb[s2][1] = (float)b1; C.sosb[s2][2] = (float)b2;
        C.sosa[s2][0] = (float)a1; C.sosa[s2][1] = (float)a2;
        double det = 1.0 + a1 + a2;
        double B0 = b1 - a1 * b0, B1 = b2 - a2 * b0;
        double z0 = (B0 + B1) / det;
        double z1 = (-a2 * B0 + (1.0 + a1) * B1) / det;
        C.zi[s2][0] = (float)(zs * z0);
        C.zi[s2][1] = (float)(zs * z1);
        zs *= (b0 + b1 + b2) / det;
    }
    return C;
}
__device__ const Coef g_coef = make_coef();

// ---------------- packed f32x2 helpers (Blackwell) ----------------
__device__ __forceinline__ u64 fma2(u64 a, u64 b, u64 c) {
    u64 d; asm("fma.rn.f32x2 %0, %1, %2, %3;" : "=l"(d) : "l"(a), "l"(b), "l"(c)); return d;
}
__device__ __forceinline__ u64 mul2(u64 a, u64 b) {
    u64 d; asm("mul.rn.f32x2 %0, %1, %2;" : "=l"(d) : "l"(a), "l"(b)); return d;
}
__device__ __forceinline__ u64 pack2(float lo, float hi) {
    u64 r; asm("mov.b64 %0, {%1, %2};" : "=l"(r) : "f"(lo), "f"(hi)); return r;
}
__device__ __forceinline__ void unpack2(u64 v, float& lo, float& hi) {
    asm("mov.b64 {%0, %1}, %2;" : "=f"(lo), "=f"(hi) : "l"(v));
}
__device__ __forceinline__ float ex2f(float x) {
    float y; asm("ex2.approx.ftz.f32 %0, %1;" : "=f"(y) : "f"(x)); return y;
}

// ---------------- init: PE table + pool zero ----------------
__global__ void eeg_init_pe_kernel() {
    int e = blockIdx.x * blockDim.x + threadIdx.x;
    if (e < TR * DM) {
        int pos = e / DM, d = e % DM;
        double div = exp(-((double)(d & ~1)) * log(10000.0) / 16.0);
        double ang = (double)pos * div;
        g_pe[e] = (float)((d & 1) ? cos(ang) : sin(ang));
    }
    if (e < BB * DM) g_pool[e] = 0.f;
}

// ---------------- stage 1: mean over selected channels ----------------
__global__ void eeg_mean_kernel(const float* __restrict__ x) {
    int idx = blockIdx.x * blockDim.x + threadIdx.x;
    if (idx >= BB * TT) return;
    int b = idx / TT, t = idx % TT;
    float s = 0.f;
    #pragma unroll
    for (int c = 0; c < 10; c++) s += x[((long)(b * 128 + d_CH[c])) * TT + t];
    g_mean[idx] = s * (1.0f / 10.0f);
}

// ---------------- stage 1b: build extended, padded, TRANSPOSED signal ----------------
__global__ void eeg_buildext_kernel(const float* __restrict__ x) {
    int idx = blockIdx.x * blockDim.x + threadIdx.x;  // t*NROWS + row
    if (idx >= TE * NROWS) return;
    int t = idx / NROWS, row = idx % NROWS;
    int b = row / NCHS, c = row % NCHS;
    const float* xp = x + ((long)(b * 128 + d_CH[c])) * TT;
    const float* mp = g_mean + (long)b * TT;
    float v;
    if (t < PADL) {
        float c0 = xp[0] - mp[0];
        int j = PADL - t;               // 21..1
        v = 2.f * c0 - (xp[j] - mp[j]);
    } else if (t < PADL + TT) {
        int j = t - PADL;
        v = xp[j] - mp[j];
    } else {
        float cl = xp[TT - 1] - mp[TT - 1];
        int j = 1998 - (t - (PADL + TT));   // 1998..1978
        v = 2.f * cl - (xp[j] - mp[j]);
    }
    g_extT[idx] = v;
}

// ---------------- biquad cascade step macro ----------------
#define BIQUAD_STEP(v, y0, y1, y2)                                   \
    {                                                                \
        y0 = fmaf(b00, (v), z00);                                    \
        z00 = fmaf(-a01, y0, fmaf(b01, (v), z01));                   \
        z01 = fmaf(-a02, y0, b02 * (v));                             \
        y1 = fmaf(b10, y0, z10);                                     \
        z10 = fmaf(-a11, y1, fmaf(b11, y0, z11));                    \
        z11 = fmaf(-a12, y1, b12 * y0);                              \
        y2 = fmaf(b20, y1, z20);                                     \
        z20 = fmaf(-a21, y2, fmaf(b21, y1, z21));                    \
        z21 = fmaf(-a22, y2, b22 * y1);                              \
    }

#define LOAD_COEFS                                                              \
    float b00 = g_coef.sosb[0][0], b01 = g_coef.sosb[0][1], b02 = g_coef.sosb[0][2]; \
    float b10 = g_coef.sosb[1][0], b11 = g_coef.sosb[1][1], b12 = g_coef.sosb[1][2]; \
    float b20 = g_coef.sosb[2][0], b21 = g_coef.sosb[2][1], b22 = g_coef.sosb[2][2]; \
    float a01 = g_coef.sosa[0][0], a02 = g_coef.sosa[0][1];                     \
    float a11 = g_coef.sosa[1][0], a12 = g_coef.sosa[1][1];                     \
    float a21 = g_coef.sosa[2][0], a22 = g_coef.sosa[2][1];

// ---------------- stage 2a: forward IIR (warp-SIMD over rows) ----------------
__global__ void eeg_filt_fwd_kernel() {
    int row = blockIdx.x * 32 + threadIdx.x;
    LOAD_COEFS;
    float x0 = g_extT[row];
    float z00 = g_coef.zi[0][0] * x0, z01 = g_coef.zi[0][1] * x0;
    float z10 = g_coef.zi[1][0] * x0, z11 = g_coef.zi[1][1] * x0;
    float z20 = g_coef.zi[2][0] * x0, z21 = g_coef.zi[2][1] * x0;
    float bufA[PF], bufB[PF];
    #pragma unroll
    for (int i = 0; i < PF; i++) bufA[i] = g_extT[i * NROWS + row];
    int t0 = 0;
    for (int blk = 0; blk < 63; blk++, t0 += PF) {
        #pragma unroll
        for (int i = 0; i < PF; i++) bufB[i] = g_extT[(t0 + PF + i) * NROWS + row];
        #pragma unroll
        for (int i = 0; i < PF; i++) {
            float v = bufA[i], y0, y1, y2;
            BIQUAD_STEP(v, y0, y1, y2);
            g_wrkT[(t0 + i) * NROWS + row] = y2;
        }
        #pragma unroll
        for (int i = 0; i < PF; i++) bufA[i] = bufB[i];
    }
    // tail: samples 2016..2041 (26)
    #pragma unroll
    for (int i = 0; i < 26; i++) {
        float v = bufA[i], y0, y1, y2;
        BIQUAD_STEP(v, y0, y1, y2);
        g_wrkT[(2016 + i) * NROWS + row] = y2;
    }
}

// ---------------- stage 2b: backward IIR + reverse/crop, transposed output ----------------
__global__ void eeg_filt_bwd_kernel() {
    int row = blockIdx.x * 32 + threadIdx.x;
    LOAD_COEFS;
    float x0 = g_wrkT[(TE - 1) * NROWS + row];
    float z00 = g_coef.zi[0][0] * x0, z01 = g_coef.zi[0][1] * x0;
    float z10 = g_coef.zi[1][0] * x0, z11 = g_coef.zi[1][1] * x0;
    float z20 = g_coef.zi[2][0] * x0, z21 = g_coef.zi[2][1] * x0;
    float bufA[PF], bufB[PF];
    #pragma unroll
    for (int i = 0; i < PF; i++) bufA[i] = g_wrkT[(TE - 1 - i) * NROWS + row];
    int t0 = 0;
    for (int blk = 0; blk < 63; blk++, t0 += PF) {
        #pragma unroll
        for (int i = 0; i < PF; i++) {
            int s = TE - 1 - (t0 + PF + i);
            s = (s > 0) ? s : 0;
            bufB[i] = g_wrkT[s * NROWS + row];
        }
        #pragma unroll
        for (int i = 0; i < PF; i++) {
            float v = bufA[i], y0, y1, y2;
            BIQUAD_STEP(v, y0, y1, y2);
            int t = t0 + i;
            int tau = 2020 - t;           // output index; valid for t in [21,2020]
            if (tau >= 0 && tau < TT) g_yfT[tau * NROWS + row] = y2;
        }
        #pragma unroll
        for (int i = 0; i < PF; i++) bufA[i] = bufB[i];
    }
    #pragma unroll
    for (int i = 0; i < 26; i++) {
        float v = bufA[i], y0, y1, y2;
        BIQUAD_STEP(v, y0, y1, y2);
        int t = 2016 + i;
        int tau = 2020 - t;
        if (tau >= 0 && tau < TT) g_yfT[tau * NROWS + row] = y2;
    }
}

// ---------------- stage 3: polyphase resample + tanh + per-row standardize ----------------
__global__ void eeg_resample_kernel() {
    __shared__ float yf[TT];
    __shared__ float tv[TR];
    __shared__ float hh[526];
    __shared__ float red[128];
    int row = blockIdx.x, tid = threadIdx.x;
    for (int t = tid; t < TT; t += 128) yf[t] = g_yfT[t * NROWS + row];
    for (int i = tid; i < 526; i += 128) hh[i] = g_fir.h[i];
    __syncthreads();
    for (int n = tid; n < TR; n += 128) {
        int A = (n + 11) * 25;
        int tlo = A - 525 + 15;
        tlo = (tlo > 0) ? (tlo >> 4) : 0;
        int thi = A >> 4;
        if (thi > TT - 1) thi = TT - 1;
        float s0 = 0.f, s1 = 0.f, s2 = 0.f, s3 = 0.f;
        int t = tlo, idx = A - 16 * tlo;
        for (; t + 3 <= thi; t += 4, idx -= 64) {
            s0 = fmaf(yf[t],     hh[idx],      s0);
            s1 = fmaf(yf[t + 1], hh[idx - 16], s1);
            s2 = fmaf(yf[t + 2], hh[idx - 32], s2);
            s3 = fmaf(yf[t + 3], hh[idx - 48], s3);
        }
        for (; t <= thi; t++, idx -= 16) s0 = fmaf(yf[t], hh[idx], s0);
        tv[n] = tanhf((s0 + s1) + (s2 + s3));
    }
    __syncthreads();
    float ls = 0.f;
    for (int n = tid; n < TR; n += 128) ls += tv[n];
    red[tid] = ls; __syncthreads();
    for (int st = 64; st > 0; st >>= 1) { if (tid < st) red[tid] += red[tid + st]; __syncthreads(); }
    float mean = red[0] * (1.f / TR);
    __syncthreads();
    float lv = 0.f;
    for (int n = tid; n < TR; n += 128) { float d = tv[n] - mean; lv = fmaf(d, d, lv); }
    red[tid] = lv; __syncthreads();
    for (int st = 64; st > 0; st >>= 1) { if (tid < st) red[tid] += red[tid + st]; __syncthreads(); }
    float var  = red[0] * (1.f / (TR - 1));
    float stdv = fmaxf(sqrtf(var), 1e-6f);
    float inv  = 1.f / stdv;
    float* dst = g_xr + (long)row * TR;
    for (int n = tid; n < TR; n += 128) dst[n] = (tv[n] - mean) * inv;
}

// ---------------- stage 4: conv1d(10->16,k3) + relu + LN0 + PE ----------------
__global__ void eeg_conv_ln_pe_kernel(const float* __restrict__ cw, const float* __restrict__ cb,
                                      const float* __restrict__ ln0g, const float* __restrict__ ln0b) {
    __shared__ float w[480];
    __shared__ float bias[16], sg[16], sb[16];
    int tid = threadIdx.x;
    for (int i = tid; i < 480; i += blockDim.x) w[i] = cw[i];
    if (tid < 16) { bias[tid] = cb[tid]; sg[tid] = ln0g[tid]; sb[tid] = ln0b[tid]; }
    __syncthreads();
    int idx = blockIdx.x * blockDim.x + tid;   // b*TR + n
    if (idx >= BB * TR) return;
    int n = idx % TR;
    float xin[10][3];
    #pragma unroll
    for (int i = 0; i < 10; i++) {
        const float* base = g_xr + ((long)(idx / TR) * NCHS + i) * TR + n;
        xin[i][0] = (n > 0)      ? base[-1] : 0.f;
        xin[i][1] = base[0];
        xin[i][2] = (n < TR - 1) ? base[1]  : 0.f;
    }
    float o[16];
    #pragma unroll
    for (int oc = 0; oc < 16; oc++) {
        float s = bias[oc];
        #pragma unroll
        for (int i = 0; i < 10; i++) {
            s = fmaf(w[oc * 30 + i * 3 + 0], xin[i][0], s);
            s = fmaf(w[oc * 30 + i * 3 + 1], xin[i][1], s);
            s = fmaf(w[oc * 30 + i * 3 + 2], xin[i][2], s);
        }
        o[oc] = fmaxf(s, 0.f);
    }
    float mu = 0.f;
    #pragma unroll
    for (int d = 0; d < 16; d++) mu += o[d];
    mu *= (1.f / 16);
    float var = 0.f;
    #pragma unroll
    for (int d = 0; d < 16; d++) { float dd = o[d] - mu; var = fmaf(dd, dd, var); }
    var *= (1.f / 16);
    float r = rsqrtf(var + 1e-5f);
    float* dst = g_h0 + (long)idx * 16;
    const float* pe = g_pe + n * 16;
    #pragma unroll
    for (int d = 0; d < 16; d++) dst[d] = fmaf((o[d] - mu) * r, sg[d], sb[d]) + pe[d];
}

// ---------------- stage 5: QKV projection (q pre-scaled by 0.25*log2e) ----------------
__global__ void eeg_qkv_kernel(const float* __restrict__ wqkv, const float* __restrict__ bqkv) {
    __shared__ float w[768];
    __shared__ float bb[48];
    int tid = threadIdx.x;
    for (int i = tid; i < 768; i += blockDim.x) w[i] = wqkv[i];
    if (tid < 48) bb[tid] = bqkv[tid];
    __syncthreads();
    int idx = blockIdx.x * blockDim.x + tid;   // b*TR + n
    float xv[16];
    const float4* src = (const float4*)(g_h0 + (long)idx * 16);
    float4 t0 = src[0], t1 = src[1], t2 = src[2], t3 = src[3];
    xv[0] = t0.x; xv[1] = t0.y; xv[2] = t0.z; xv[3] = t0.w;
    xv[4] = t1.x; xv[5] = t1.y; xv[6] = t1.z; xv[7] = t1.w;
    xv[8] = t2.x; xv[9] = t2.y; xv[10] = t2.z; xv[11] = t2.w;
    xv[12] = t3.x; xv[13] = t3.y; xv[14] = t3.z; xv[15] = t3.w;
    float* qd = g_q + (long)idx * 16;
    float* kd = g_k + (long)idx * 16;
    float* vd = g_v + (long)idx * 16;
    const float QSCALE = 0.25f * 1.4426950408889634f;
    #pragma unroll
    for (int j = 0; j < 16; j++) {
        float sq = bb[j], sk = bb[16 + j], sv = bb[32 + j];
        #pragma unroll
        for (int d = 0; d < 16; d++) {
            sq = fmaf(w[j * 16 + d],        xv[d], sq);
            sk = fmaf(w[(16 + j) * 16 + d], xv[d], sk);
            sv = fmaf(w[(32 + j) * 16 + d], xv[d], sv);
        }
        qd[j] = sq * QSCALE;
        kd[j] = sk;
        vd[j] = sv;
    }
}

// ---------------- LN helper ----------------
__device__ __forceinline__ void ln16(float* v, const float* g, const float* b) {
    float mu = 0.f;
    #pragma unroll
    for (int d = 0; d < 16; d++) mu += v[d];
    mu *= (1.f / 16);
    float var = 0.f;
    #pragma unroll
    for (int d = 0; d < 16; d++) { float dd = v[d] - mu; var = fmaf(dd, dd, var); }
    var *= (1.f / 16);
    float r = rsqrtf(var + 1e-5f);
    #pragma unroll
    for (int d = 0; d < 16; d++) v[d] = fmaf((v[d] - mu) * r, g[d], b[d]);
}

// ---------------- stage 6: attention + wo + LN1 + FFN + LN2 + pool ----------------
__global__ void eeg_attn_kernel(const float* __restrict__ wo, const float* __restrict__ bo,
                                const float* __restrict__ w1, const float* __restrict__ b1,
                                const float* __restrict__ w2, const float* __restrict__ b2,
                                const float* __restrict__ l1g, const float* __restrict__ l1b,
                                const float* __restrict__ l2g, const float* __restrict__ l2b) {
    __shared__ __align__(16) float Ks[128 * 16];
    __shared__ __align__(16) float Vs[128 * 16];
    __shared__ float swo[256], sbo[16], sw1[512], sb1[32], sw2[512], sb2[16];
    __shared__ float sl1g[16], sl1b[16], sl2g[16], sl2b[16];
    int tid = threadIdx.x;
    for (int i = tid; i < 256; i += 128) swo[i] = wo[i];
    for (int i = tid; i < 512; i += 128) { sw1[i] = w1[i]; sw2[i] = w2[i]; }
    if (tid < 16) {
        sbo[tid] = bo[tid]; sb2[tid] = b2[tid];
        sl1g[tid] = l1g[tid]; sl1b[tid] = l1b[tid];
        sl2g[tid] = l2g[tid]; sl2b[tid] = l2b[tid];
    }
    if (tid < 32) sb1[tid] = b1[tid];

    int b = blockIdx.x / 10, qt = blockIdx.x % 10;
    int qn = qt * 128 + tid;
    long qbase = ((long)b * TR + qn) * 16;

    u64 q2[8];
    {
        const ulonglong2* s = (const ulonglong2*)(g_q + qbase);
        ulonglong2 a0 = s[0], a1 = s[1], a2 = s[2], a3 = s[3];
        q2[0] = a0.x; q2[1] = a0.y; q2[2] = a1.x; q2[3] = a1.y;
        q2[4] = a2.x; q2[5] = a2.y; q2[6] = a3.x; q2[7] = a3.y;
    }
    u64 acc2[8];
    u64 zero2 = pack2(0.f, 0.f);
    #pragma unroll
    for (int d = 0; d < 8; d++) acc2[d] = zero2;
    float l = 0.f;

    for (int kb = 0; kb < 10; kb++) {
        __syncthreads();
        long kbase = ((long)b * TR + kb * 128 + tid) * 16;
        {
            const float4* sk = (const float4*)(g_k + kbase);
            float4* dk = (float4*)(Ks + tid * 16);
            dk[0] = sk[0]; dk[1] = sk[1]; dk[2] = sk[2]; dk[3] = sk[3];
            const float4* sv = (const float4*)(g_v + kbase);
            float4* dv = (float4*)(Vs + tid * 16);
            dv[0] = sv[0]; dv[1] = sv[1]; dv[2] = sv[2]; dv[3] = sv[3];
        }
        __syncthreads();
        #pragma unroll 2
        for (int j = 0; j < 128; j++) {
            const ulonglong2* kr = (const ulonglong2*)(Ks + j * 16);
            ulonglong2 ka = kr[0], kc = kr[1], ke = kr[2], kg = kr[3];
            u64 sa = mul2(q2[0], ka.x);
            u64 sb_ = mul2(q2[4], ke.x);
            sa  = fma2(q2[1], ka.y, sa);
            sb_ = fma2(q2[5], ke.y, sb_);
            sa  = fma2(q2[2], kc.x, sa);
            sb_ = fma2(q2[6], kg.x, sb_);
            sa  = fma2(q2[3], kc.y, sa);
            sb_ = fma2(q2[7], kg.y, sb_);
            float a0, a1, b0, b1;
            unpack2(sa, a0, a1);
            unpack2(sb_, b0, b1);
            float s = (a0 + a1) + (b0 + b1);
            float p = ex2f(s);
            l += p;
            u64 p2 = pack2(p, p);
            const ulonglong2* vr = (const ulonglong2*)(Vs + j * 16);
            ulonglong2 va = vr[0], vc = vr[1], ve = vr[2], vg = vr[3];
            acc2[0] = fma2(p2, va.x, acc2[0]);
            acc2[1] = fma2(p2, va.y, acc2[1]);
            acc2[2] = fma2(p2, vc.x, acc2[2]);
            acc2[3] = fma2(p2, vc.y, acc2[3]);
            acc2[4] = fma2(p2, ve.x, acc2[4]);
            acc2[5] = fma2(p2, ve.y, acc2[5]);
            acc2[6] = fma2(p2, vg.x, acc2[6]);
            acc2[7] = fma2(p2, vg.y, acc2[7]);
        }
    }
    float inv = 1.f / l;
    float ov[16];
    #pragma unroll
    for (int d = 0; d < 8; d++) {
        float lo, hi;
        unpack2(acc2[d], lo, hi);
        ov[2 * d]     = lo * inv;
        ov[2 * d + 1] = hi * inv;
    }
    float h0v[16];
    {
        const float4* hs = (const float4*)(g_h0 + qbase);
        float4 a0 = hs[0], a1 = hs[1], a2 = hs[2], a3 = hs[3];
        h0v[0] = a0.x; h0v[1] = a0.y; h0v[2] = a0.z; h0v[3] = a0.w;
        h0v[4] = a1.x; h0v[5] = a1.y; h0v[6] = a1.z; h0v[7] = a1.w;
        h0v[8] = a2.x; h0v[9] = a2.y; h0v[10] = a2.z; h0v[11] = a2.w;
        h0v[12] = a3.x; h0v[13] = a3.y; h0v[14] = a3.z; h0v[15] = a3.w;
    }
    float x1[16];
    #pragma unroll
    for (int d = 0; d < 16; d++) {
        float s = sbo[d];
        #pragma unroll
        for (int e = 0; e < 16; e++) s = fmaf(swo[d * 16 + e], ov[e], s);
        x1[d] = h0v[d] + s;
    }
    ln16(x1, sl1g, sl1b);
    float f[16];
    #pragma unroll
    for (int d = 0; d < 16; d++) f[d] = sb2[d];
    #pragma unroll
    for (int j = 0; j < 32; j++) {
        float t = sb1[j];
        #pragma unroll
        for (int e = 0; e < 16; e++) t = fmaf(sw1[j * 16 + e], x1[e], t);
        t = fmaxf(t, 0.f);
        #pragma unroll
        for (int d = 0; d < 16; d++) f[d] = fmaf(sw2[d * 32 + j], t, f[d]);
    }
    float x2[16];
    #pragma unroll
    for (int d = 0; d < 16; d++) x2[d] = x1[d] + f[d];
    ln16(x2, sl2g, sl2b);
    __syncthreads();
    float* R = Ks;
    #pragma unroll
    for (int d = 0; d < 16; d++) R[tid * 16 + d] = x2[d];
    __syncthreads();
    for (int st = 64; st > 0; st >>= 1) {
        if (tid < st) {
            #pragma unroll
            for (int d = 0; d < 16; d++) R[tid * 16 + d] += R[(tid + st) * 16 + d];
        }
        __syncthreads();
    }
    if (tid < 16) atomicAdd(&g_pool[b * 16 + tid], R[tid]);
}

// ---------------- stage 7: head ----------------
__global__ void eeg_head_kernel(const float* __restrict__ wfc, const float* __restrict__ bfc,
                                float* __restrict__ out) {
    int b = threadIdx.x;
    if (b < BB) {
        float s = 0.f;
        #pragma unroll
        for (int d = 0; d < 16; d++) s = fmaf(g_pool[b * 16 + d], wfc[d], s);
        out[b] = s * (1.f / (float)TR) + bfc[0];
    }
}

// ---------------- launch ----------------
extern "C" void kernel_launch(void* const* d_in, const int* in_sizes, int n_in,
                              void* d_out, int out_size) {
    const float* x      = (const float*)d_in[0];
    const float* conv_w = (const float*)d_in[1];
    const float* conv_b = (const float*)d_in[2];
    const float* ln0g   = (const float*)d_in[3];
    const float* ln0b   = (const float*)d_in[4];
    const float* wqkv   = (const float*)d_in[5];
    const float* bqkv   = (const float*)d_in[6];
    const float* wo     = (const float*)d_in[7];
    const float* bo     = (const float*)d_in[8];
    const float* w1     = (const float*)d_in[9];
    const float* b1     = (const float*)d_in[10];
    const float* w2     = (const float*)d_in[11];
    const float* b2     = (const float*)d_in[12];
    const float* l1g    = (const float*)d_in[13];
    const float* l1b    = (const float*)d_in[14];
    const float* l2g    = (const float*)d_in[15];
    const float* l2b    = (const float*)d_in[16];
    const float* wfc    = (const float*)d_in[17];
    const float* bfc    = (const float*)d_in[18];
    float* out = (float*)d_out;

    eeg_init_pe_kernel<<<(TR * DM + 127) / 128, 128>>>();
    eeg_mean_kernel<<<(BB * TT + 255) / 256, 256>>>(x);
    eeg_buildext_kernel<<<(TE * NROWS + 255) / 256, 256>>>(x);
    eeg_filt_fwd_kernel<<<NROWS / 32, 32>>>();
    eeg_filt_bwd_kernel<<<NROWS / 32, 32>>>();
    eeg_resample_kernel<<<NROWS, 128>>>();
    eeg_conv_ln_pe_kernel<<<(BB * TR) / 256, 256>>>(conv_w, conv_b, ln0g, ln0b);
    eeg_qkv_kernel<<<(BB * TR) / 128, 128>>>(wqkv, bqkv);
    eeg_attn_kernel<<<NROWS, 128>>>(wo, bo, w1, b1, w2, b2, l1g, l1b, l2g, l2b);
    eeg_head_kernel<<<1, 64>>>(wfc, bfc, out);
}